// round 1
// baseline (speedup 1.0000x reference)
#include <cuda_runtime.h>
#include <cuda_bf16.h>

// ---------------------------------------------------------------------------
// S5 SSM: ys = 2*Re( scan(Lam_bar, B_bar@u) @ C^T ) + d*u
// Stages:
//   prep_params : discretization (a = Lam_bar, a^T, B scale) [P threads]
//   prep_weights: W1[h][2p±] = B_bar re/im ; W2[2p±][h] = ±2*C re/im
//   gemm<false> : Bu_flat[L][512] = u[L][512] @ W1[512][512]
//   scan        : per-chunk local recurrence x = a*x + Bu (in place)
//   carry       : Kogge-Stone scan of chunk end-states with multiplier a^T
//   correct     : x[l] += a^{t+1} * carry_in(chunk)
//   gemm<true>  : out = xs_flat @ W2 + d*u
// ---------------------------------------------------------------------------

#define L_SEQ   32768
#define H_FEAT  512
#define P_STATE 256
#define N2      512          // 2*P
#define C_CHUNKS 512
#define T_CHUNK  64          // L_SEQ / C_CHUNKS
#define SQ_POW   6           // log2(T_CHUNK)

// Scratch (static __device__ allocations; no cudaMalloc allowed)
__device__ float2 g_Bu[L_SEQ * P_STATE];              // 64 MB: Bu then xs in place
__device__ float  g_W1[H_FEAT * N2];                  // 1 MB
__device__ float  g_W2[N2 * H_FEAT];                  // 1 MB
__device__ float2 g_a[P_STATE];
__device__ float2 g_aT[P_STATE];
__device__ float2 g_Bscale[P_STATE];
__device__ float2 g_end[C_CHUNKS * P_STATE];
__device__ float2 g_carry[C_CHUNKS * P_STATE];

__device__ __forceinline__ float2 cmul(float2 a, float2 b) {
    return make_float2(a.x * b.x - a.y * b.y, a.x * b.y + a.y * b.x);
}

// ---------------------------------------------------------------------------
// Discretization parameters
// ---------------------------------------------------------------------------
__global__ void prep_params(const float* __restrict__ lr,
                            const float* __restrict__ li,
                            const float* __restrict__ delta) {
    int p = threadIdx.x;
    float step = expf(delta[p]);
    float hs = 0.5f * step;
    // BL = 1 / (1 - hs*Lam)
    float dr = 1.0f - hs * lr[p];
    float di = -hs * li[p];
    float inv = 1.0f / (dr * dr + di * di);
    float2 BL = make_float2(dr * inv, -di * inv);
    float2 num = make_float2(1.0f + hs * lr[p], hs * li[p]);
    float2 a = cmul(BL, num);                    // Lam_bar
    g_a[p] = a;
    g_Bscale[p] = make_float2(BL.x * step, BL.y * step);
    float2 t = a;
    #pragma unroll
    for (int i = 0; i < SQ_POW; i++) t = cmul(t, t);   // a^T_CHUNK
    g_aT[p] = t;
}

__global__ void prep_weights(const float* __restrict__ b,
                             const float* __restrict__ c) {
    int p = blockIdx.x;        // 0..255
    int h = threadIdx.x;       // 0..511
    float2 bs = g_Bscale[p];
    float br = b[(p * H_FEAT + h) * 2 + 0];
    float bi = b[(p * H_FEAT + h) * 2 + 1];
    g_W1[h * N2 + 2 * p]     = bs.x * br - bs.y * bi;
    g_W1[h * N2 + 2 * p + 1] = bs.x * bi + bs.y * br;
    g_W2[(2 * p) * H_FEAT + h]     =  2.0f * c[(h * P_STATE + p) * 2 + 0];
    g_W2[(2 * p + 1) * H_FEAT + h] = -2.0f * c[(h * P_STATE + p) * 2 + 1];
}

// ---------------------------------------------------------------------------
// SIMT fp32 GEMM, M=32768 N=512 K=512, 128x128 tile, 8x8/thread,
// packed fma.rn.f32x2 (pairs along M).
// ---------------------------------------------------------------------------
template <bool EPI>
__global__ void __launch_bounds__(256)
gemm_kernel(const float* __restrict__ A, const float* __restrict__ B,
            float* __restrict__ Cout, const float* __restrict__ U,
            const float* __restrict__ D) {
    __shared__ float As[16][130];   // [k][m], pad 130 keeps 8B align + no store conflicts
    __shared__ float Bs[16][128];   // [k][n]

    const int tid = threadIdx.x;
    const int tx = tid & 15;        // N lane
    const int ty = tid >> 4;        // M lane
    const int bm = blockIdx.y * 128;
    const int bn = blockIdx.x * 128;

    // A tile load mapping: thread -> (row ar, k-half ak)
    const int ar = tid >> 1;
    const int ak = (tid & 1) * 8;
    // B tile load mapping: thread -> (row kb & kb+8, 4 cols at cb)
    const int kb = tid >> 5;
    const int cb = (tid & 31) * 4;

    unsigned long long acc[4][8];
    #pragma unroll
    for (int q = 0; q < 4; q++)
        #pragma unroll
        for (int j = 0; j < 8; j++) acc[q][j] = 0ULL;

    for (int kt = 0; kt < 512; kt += 16) {
        const float4 a0 = *(const float4*)&A[(size_t)(bm + ar) * 512 + kt + ak];
        const float4 a1 = *(const float4*)&A[(size_t)(bm + ar) * 512 + kt + ak + 4];
        const float4 b0 = *(const float4*)&B[(size_t)(kt + kb) * 512 + bn + cb];
        const float4 b1 = *(const float4*)&B[(size_t)(kt + kb + 8) * 512 + bn + cb];

        As[ak + 0][ar] = a0.x; As[ak + 1][ar] = a0.y;
        As[ak + 2][ar] = a0.z; As[ak + 3][ar] = a0.w;
        As[ak + 4][ar] = a1.x; As[ak + 5][ar] = a1.y;
        As[ak + 6][ar] = a1.z; As[ak + 7][ar] = a1.w;
        *(float4*)&Bs[kb][cb] = b0;
        *(float4*)&Bs[kb + 8][cb] = b1;
        __syncthreads();

        #pragma unroll
        for (int k = 0; k < 16; k++) {
            unsigned long long a2[4];
            #pragma unroll
            for (int q = 0; q < 4; q++)
                a2[q] = *(const unsigned long long*)&As[k][ty * 8 + 2 * q];
            #pragma unroll
            for (int j = 0; j < 8; j++) {
                float bv = Bs[k][j * 16 + tx];
                unsigned long long b2;
                asm("mov.b64 %0, {%1, %2};" : "=l"(b2) : "f"(bv), "f"(bv));
                #pragma unroll
                for (int q = 0; q < 4; q++)
                    asm("fma.rn.f32x2 %0, %1, %2, %0;"
                        : "+l"(acc[q][j]) : "l"(a2[q]), "l"(b2));
            }
        }
        __syncthreads();
    }

    #pragma unroll
    for (int j = 0; j < 8; j++) {
        const int col = bn + j * 16 + tx;
        float dv = 0.0f;
        if (EPI) dv = D[col];
        #pragma unroll
        for (int q = 0; q < 4; q++) {
            const int row = bm + ty * 8 + 2 * q;
            float lo, hi;
            asm("mov.b64 {%0, %1}, %2;" : "=f"(lo), "=f"(hi) : "l"(acc[q][j]));
            if (EPI) {
                lo = fmaf(dv, U[(size_t)row * 512 + col], lo);
                hi = fmaf(dv, U[(size_t)(row + 1) * 512 + col], hi);
            }
            Cout[(size_t)row * 512 + col] = lo;
            Cout[(size_t)(row + 1) * 512 + col] = hi;
        }
    }
}

// ---------------------------------------------------------------------------
// Chunked recurrence scan (local, zero initial condition), in place over g_Bu
// ---------------------------------------------------------------------------
__global__ void __launch_bounds__(256) scan_kernel() {
    const int p = threadIdx.x;
    const int c = blockIdx.x;
    const float2 a = g_a[p];
    float2 x = make_float2(0.0f, 0.0f);
    size_t base = (size_t)c * T_CHUNK * P_STATE + p;
    #pragma unroll 8
    for (int t = 0; t < T_CHUNK; t++) {
        float2 v = g_Bu[base + (size_t)t * P_STATE];
        float xr = fmaf(a.x, x.x, fmaf(-a.y, x.y, v.x));
        float xi = fmaf(a.x, x.y, fmaf(a.y, x.x, v.y));
        x = make_float2(xr, xi);
        g_Bu[base + (size_t)t * P_STATE] = x;
    }
    g_end[c * P_STATE + p] = x;
}

// Kogge-Stone inclusive scan over chunk end-states: S_c = end_c + aT * S_{c-1}
__global__ void __launch_bounds__(C_CHUNKS) carry_kernel() {
    __shared__ float2 s[C_CHUNKS];
    const int p = blockIdx.x;
    const int c = threadIdx.x;
    const float2 aT = g_aT[p];
    s[c] = g_end[c * P_STATE + p];
    float2 m = aT;
    __syncthreads();
    for (int d = 1; d < C_CHUNKS; d <<= 1) {
        float2 other = make_float2(0.0f, 0.0f);
        if (c >= d) other = s[c - d];
        __syncthreads();
        if (c >= d) {
            float2 cur = s[c];
            s[c] = make_float2(cur.x + m.x * other.x - m.y * other.y,
                               cur.y + m.x * other.y + m.y * other.x);
        }
        m = cmul(m, m);
        __syncthreads();
    }
    float2 ci = make_float2(0.0f, 0.0f);
    if (c > 0) ci = s[c - 1];
    g_carry[c * P_STATE + p] = ci;
}

// x_global[l] = x_local[l] + a^{t+1} * carry_in(chunk)
__global__ void __launch_bounds__(256) correct_kernel() {
    const int p = threadIdx.x;
    const int c = blockIdx.x + 1;   // chunk 0 has zero carry
    const float2 a = g_a[p];
    float2 cc = cmul(a, g_carry[c * P_STATE + p]);   // a^{1} * carry
    size_t base = (size_t)c * T_CHUNK * P_STATE + p;
    #pragma unroll 8
    for (int t = 0; t < T_CHUNK; t++) {
        float2 v = g_Bu[base + (size_t)t * P_STATE];
        v.x += cc.x;
        v.y += cc.y;
        g_Bu[base + (size_t)t * P_STATE] = v;
        cc = cmul(cc, a);
    }
}

// ---------------------------------------------------------------------------
extern "C" void kernel_launch(void* const* d_in, const int* in_sizes, int n_in,
                              void* d_out, int out_size) {
    const float* u     = (const float*)d_in[0];   // [L, H]
    const float* lr    = (const float*)d_in[1];   // [P]
    const float* li    = (const float*)d_in[2];   // [P]
    const float* b     = (const float*)d_in[3];   // [P, H, 2]
    const float* c     = (const float*)d_in[4];   // [H, P, 2]
    const float* d     = (const float*)d_in[5];   // [H]
    const float* delta = (const float*)d_in[6];   // [P, 1]
    float* out = (float*)d_out;

    float2* bu2;  cudaGetSymbolAddress((void**)&bu2, g_Bu);
    float* w1;    cudaGetSymbolAddress((void**)&w1, g_W1);
    float* w2;    cudaGetSymbolAddress((void**)&w2, g_W2);
    float* buf = (float*)bu2;

    prep_params<<<1, P_STATE>>>(lr, li, delta);
    prep_weights<<<P_STATE, H_FEAT>>>(b, c);
    gemm_kernel<false><<<dim3(4, 256), 256>>>(u, w1, buf, nullptr, nullptr);
    scan_kernel<<<C_CHUNKS, P_STATE>>>();
    carry_kernel<<<P_STATE, C_CHUNKS>>>();
    correct_kernel<<<C_CHUNKS - 1, P_STATE>>>();
    gemm_kernel<true><<<dim3(4, 256), 256>>>(buf, w2, out, u, d);
}

// round 3
// speedup vs baseline: 1.8780x; 1.8780x over previous
#include <cuda_runtime.h>
#include <cuda_bf16.h>
#include <cstdint>

// ---------------------------------------------------------------------------
// S5 SSM: ys = 2*Re( scan(Lam_bar, B_bar@u) @ C^T ) + d*u
// GEMMs: warp-level mma.sync bf16 (hi/lo split, 3 terms, fp32 accum)
//   -- tcgen05 is unavailable: harness ptxas targets family 'sm_103'
// ---------------------------------------------------------------------------

#define L_SEQ   32768
#define H_FEAT  512
#define P_STATE 256
#define N2      512
#define C_CHUNKS 512
#define T_CHUNK  64
#define SQ_POW   6

#define BM 128
#define BN 128
#define BK 32              // bf16 elems per K-chunk
#define NCH 16             // 512 / 32
#define ROWB 80            // padded smem row bytes (64B data + 16B pad)
#define OP_BYTES (128 * ROWB)          // 10240 per operand tile
#define STG_BYTES (4 * OP_BYTES)       // Ah, Al, Bh, Bl
#define NSTAGE 3
#define SMEMB (NSTAGE * STG_BYTES)     // 122880

// Scratch (static __device__; no cudaMalloc allowed)
__device__ float2 g_Bu[L_SEQ * P_STATE];               // 64 MB (Bu then xs)
__device__ __nv_bfloat16 g_Ahi[L_SEQ * N2];            // 32 MB
__device__ __nv_bfloat16 g_Alo[L_SEQ * N2];            // 32 MB
__device__ __nv_bfloat16 g_W1hi[N2 * H_FEAT], g_W1lo[N2 * H_FEAT];
__device__ __nv_bfloat16 g_W2hi[H_FEAT * N2], g_W2lo[H_FEAT * N2];
__device__ float2 g_a[P_STATE];
__device__ float2 g_aT[P_STATE];
__device__ float2 g_Bscale[P_STATE];
__device__ float2 g_end[C_CHUNKS * P_STATE];
__device__ float2 g_carry[C_CHUNKS * P_STATE];

__device__ __forceinline__ float2 cmul(float2 a, float2 b) {
    return make_float2(a.x * b.x - a.y * b.y, a.x * b.y + a.y * b.x);
}

__device__ __forceinline__ uint32_t smem_u32(const void* p) {
    uint32_t a;
    asm("{ .reg .u64 t; cvta.to.shared.u64 t, %1; cvt.u32.u64 %0, t; }"
        : "=r"(a) : "l"(p));
    return a;
}
__device__ __forceinline__ void cp16(uint32_t dst, const void* src) {
    asm volatile("cp.async.cg.shared.global [%0], [%1], 16;" :: "r"(dst), "l"(src));
}
__device__ __forceinline__ void ldsm4(uint32_t* r, uint32_t addr) {
    asm volatile("ldmatrix.sync.aligned.m8n8.x4.shared.b16 {%0,%1,%2,%3}, [%4];"
                 : "=r"(r[0]), "=r"(r[1]), "=r"(r[2]), "=r"(r[3]) : "r"(addr));
}
__device__ __forceinline__ void mma16816(float* d, const uint32_t* a,
                                         uint32_t b0, uint32_t b1) {
    asm volatile(
        "mma.sync.aligned.m16n8k16.row.col.f32.bf16.bf16.f32 "
        "{%0,%1,%2,%3}, {%4,%5,%6,%7}, {%8,%9}, {%0,%1,%2,%3};"
        : "+f"(d[0]), "+f"(d[1]), "+f"(d[2]), "+f"(d[3])
        : "r"(a[0]), "r"(a[1]), "r"(a[2]), "r"(a[3]), "r"(b0), "r"(b1));
}

// ---------------------------------------------------------------------------
// Discretization parameters
// ---------------------------------------------------------------------------
__global__ void prep_params(const float* __restrict__ lr,
                            const float* __restrict__ li,
                            const float* __restrict__ delta) {
    int p = threadIdx.x;
    float step = expf(delta[p]);
    float hs = 0.5f * step;
    float dr = 1.0f - hs * lr[p];
    float di = -hs * li[p];
    float inv = 1.0f / (dr * dr + di * di);
    float2 BL = make_float2(dr * inv, -di * inv);
    float2 num = make_float2(1.0f + hs * lr[p], hs * li[p]);
    float2 a = cmul(BL, num);
    g_a[p] = a;
    g_Bscale[p] = make_float2(BL.x * step, BL.y * step);
    float2 t = a;
    #pragma unroll
    for (int i = 0; i < SQ_POW; i++) t = cmul(t, t);
    g_aT[p] = t;
}

__device__ __forceinline__ void store_split(__nv_bfloat16* hi, __nv_bfloat16* lo,
                                            int idx, float v) {
    __nv_bfloat16 h = __float2bfloat16(v);
    hi[idx] = h;
    lo[idx] = __float2bfloat16(v - __bfloat162float(h));
}

__global__ void prep_weights(const float* __restrict__ b,
                             const float* __restrict__ c) {
    int p = blockIdx.x;        // 0..255
    int h = threadIdx.x;       // 0..511
    float2 bs = g_Bscale[p];
    float br = b[(p * H_FEAT + h) * 2 + 0];
    float bi = b[(p * H_FEAT + h) * 2 + 1];
    // W1 as [n=2p|2p+1][k=h]  (mma B operand: [N][K], K contiguous)
    store_split(g_W1hi, g_W1lo, (2 * p) * H_FEAT + h, bs.x * br - bs.y * bi);
    store_split(g_W1hi, g_W1lo, (2 * p + 1) * H_FEAT + h, bs.x * bi + bs.y * br);
    // W2 as [n=h][k=2p|2p+1]
    store_split(g_W2hi, g_W2lo, h * N2 + 2 * p,      2.0f * c[(h * P_STATE + p) * 2 + 0]);
    store_split(g_W2hi, g_W2lo, h * N2 + 2 * p + 1, -2.0f * c[(h * P_STATE + p) * 2 + 1]);
}

// fp32 -> bf16 hi/lo split (grid-stride, float4)
__global__ void convert_split(const float4* __restrict__ src,
                              uint2* __restrict__ hi, uint2* __restrict__ lo, int n4) {
    int stride = gridDim.x * blockDim.x;
    for (int i = blockIdx.x * blockDim.x + threadIdx.x; i < n4; i += stride) {
        float4 v = src[i];
        __nv_bfloat162 h0 = __floats2bfloat162_rn(v.x, v.y);
        __nv_bfloat162 h1 = __floats2bfloat162_rn(v.z, v.w);
        float2 f0 = __bfloat1622float2(h0);
        float2 f1 = __bfloat1622float2(h1);
        __nv_bfloat162 l0 = __floats2bfloat162_rn(v.x - f0.x, v.y - f0.y);
        __nv_bfloat162 l1 = __floats2bfloat162_rn(v.z - f1.x, v.w - f1.y);
        hi[i] = make_uint2(*(uint32_t*)&h0, *(uint32_t*)&h1);
        lo[i] = make_uint2(*(uint32_t*)&l0, *(uint32_t*)&l1);
    }
}

// ---------------------------------------------------------------------------
// bf16 split GEMM: C[M,512] = (Ah+Al)[M,K] x (Bh+Bl)[N,K]^T
// block 128x128, 256 thr, warp 32x64, K-chunks of 32, cp.async 3-stage
// ---------------------------------------------------------------------------
template <bool EPI>
__global__ void __launch_bounds__(256, 1)
gemm_bf16(const __nv_bfloat16* __restrict__ Ahi, const __nv_bfloat16* __restrict__ Alo,
          const __nv_bfloat16* __restrict__ Bhi, const __nv_bfloat16* __restrict__ Blo,
          float* __restrict__ Cout, const float* __restrict__ U,
          const float* __restrict__ D) {
    extern __shared__ char smem[];
    const uint32_t sb = smem_u32(smem);
    const int tid = threadIdx.x;
    const int wid = tid >> 5, lane = tid & 31;
    const int warpM = wid & 3, warpN = wid >> 2;       // 4x2 warp grid
    const int bm = blockIdx.y * BM;
    const int bn = blockIdx.x * BN;

    const char* bases[4] = {
        (const char*)Ahi + (size_t)bm * 1024,
        (const char*)Alo + (size_t)bm * 1024,
        (const char*)Bhi + (size_t)bn * 1024,
        (const char*)Blo + (size_t)bn * 1024 };

    auto load_chunk = [&](int kt, int st) {
        const uint32_t base = sb + st * STG_BYTES;
        const int kb = kt * 64;                        // byte offset into row
        const int s = tid & 3;
        #pragma unroll
        for (int j = 0; j < 8; j++) {
            const int op = j >> 1;
            const int r = (tid >> 2) + ((j & 1) << 6);
            cp16(base + op * OP_BYTES + r * ROWB + s * 16,
                 bases[op] + (size_t)r * 1024 + kb + s * 16);
        }
        asm volatile("cp.async.commit_group;");
    };

    load_chunk(0, 0);
    load_chunk(1, 1);

    float acc[2][8][4];
    #pragma unroll
    for (int im = 0; im < 2; im++)
        #pragma unroll
        for (int in = 0; in < 8; in++)
            #pragma unroll
            for (int q = 0; q < 4; q++) acc[im][in][q] = 0.0f;

    // ldmatrix lane offsets
    const uint32_t a_lo = (lane & 15) * ROWB + (lane >> 4) * 16;
    const uint32_t b_lo = ((lane & 7) + ((lane >> 4) << 3)) * ROWB +
                          ((lane >> 3) & 1) * 16;

    for (int kt = 0; kt < NCH; kt++) {
        const int st = kt % NSTAGE;
        if (kt == NCH - 1) asm volatile("cp.async.wait_group 0;");
        else               asm volatile("cp.async.wait_group 1;");
        __syncthreads();
        if (kt + 2 < NCH) load_chunk(kt + 2, (kt + 2) % NSTAGE);

        const uint32_t sg = sb + st * STG_BYTES;
        #pragma unroll
        for (int ks = 0; ks < 2; ks++) {
            const uint32_t ksb = ks * 32;
            uint32_t ah[2][4], al[2][4], bh[4][4], bl[4][4];
            #pragma unroll
            for (int im = 0; im < 2; im++) {
                const uint32_t ao = (warpM * 32 + im * 16) * ROWB + a_lo + ksb;
                ldsm4(ah[im], sg + ao);
                ldsm4(al[im], sg + OP_BYTES + ao);
            }
            #pragma unroll
            for (int ip = 0; ip < 4; ip++) {
                const uint32_t bo = (warpN * 64 + ip * 16) * ROWB + b_lo + ksb;
                ldsm4(bh[ip], sg + 2 * OP_BYTES + bo);
                ldsm4(bl[ip], sg + 3 * OP_BYTES + bo);
            }
            #pragma unroll
            for (int im = 0; im < 2; im++)
                #pragma unroll
                for (int ip = 0; ip < 4; ip++) {
                    mma16816(acc[im][2 * ip],     ah[im], bh[ip][0], bh[ip][1]);
                    mma16816(acc[im][2 * ip + 1], ah[im], bh[ip][2], bh[ip][3]);
                    mma16816(acc[im][2 * ip],     ah[im], bl[ip][0], bl[ip][1]);
                    mma16816(acc[im][2 * ip + 1], ah[im], bl[ip][2], bl[ip][3]);
                    mma16816(acc[im][2 * ip],     al[im], bh[ip][0], bh[ip][1]);
                    mma16816(acc[im][2 * ip + 1], al[im], bh[ip][2], bh[ip][3]);
                }
        }
    }

    // Epilogue: direct fp32 stores (float2 per frag-half)
    #pragma unroll
    for (int im = 0; im < 2; im++) {
        const int row0 = bm + warpM * 32 + im * 16 + (lane >> 2);
        #pragma unroll
        for (int in = 0; in < 8; in++) {
            const int col = bn + warpN * 64 + in * 8 + (lane & 3) * 2;
            float2 v0 = make_float2(acc[im][in][0], acc[im][in][1]);
            float2 v1 = make_float2(acc[im][in][2], acc[im][in][3]);
            if constexpr (EPI) {
                float2 dv = *(const float2*)&D[col];
                float2 u0 = *(const float2*)&U[(size_t)row0 * H_FEAT + col];
                float2 u1 = *(const float2*)&U[(size_t)(row0 + 8) * H_FEAT + col];
                v0.x = fmaf(dv.x, u0.x, v0.x); v0.y = fmaf(dv.y, u0.y, v0.y);
                v1.x = fmaf(dv.x, u1.x, v1.x); v1.y = fmaf(dv.y, u1.y, v1.y);
            }
            *(float2*)&Cout[(size_t)row0 * H_FEAT + col] = v0;
            *(float2*)&Cout[(size_t)(row0 + 8) * H_FEAT + col] = v1;
        }
    }
}

// ---------------------------------------------------------------------------
// Chunked recurrence scan
// ---------------------------------------------------------------------------
__global__ void __launch_bounds__(256) scan_kernel() {
    const int p = threadIdx.x;
    const int c = blockIdx.x;
    const float2 a = g_a[p];
    float2 x = make_float2(0.0f, 0.0f);
    size_t base = (size_t)c * T_CHUNK * P_STATE + p;
    #pragma unroll 8
    for (int t = 0; t < T_CHUNK; t++) {
        float2 v = g_Bu[base + (size_t)t * P_STATE];
        float xr = fmaf(a.x, x.x, fmaf(-a.y, x.y, v.x));
        float xi = fmaf(a.x, x.y, fmaf(a.y, x.x, v.y));
        x = make_float2(xr, xi);
        g_Bu[base + (size_t)t * P_STATE] = x;
    }
    g_end[c * P_STATE + p] = x;
}

__global__ void __launch_bounds__(C_CHUNKS) carry_kernel() {
    __shared__ float2 s[C_CHUNKS];
    const int p = blockIdx.x;
    const int c = threadIdx.x;
    const float2 aT = g_aT[p];
    s[c] = g_end[c * P_STATE + p];
    float2 m = aT;
    __syncthreads();
    for (int d = 1; d < C_CHUNKS; d <<= 1) {
        float2 other = make_float2(0.0f, 0.0f);
        if (c >= d) other = s[c - d];
        __syncthreads();
        if (c >= d) {
            float2 cur = s[c];
            s[c] = make_float2(cur.x + m.x * other.x - m.y * other.y,
                               cur.y + m.x * other.y + m.y * other.x);
        }
        m = cmul(m, m);
        __syncthreads();
    }
    float2 ci = make_float2(0.0f, 0.0f);
    if (c > 0) ci = s[c - 1];
    g_carry[c * P_STATE + p] = ci;
}

__global__ void __launch_bounds__(256) correct_kernel() {
    const int p = threadIdx.x;
    const int c = blockIdx.x + 1;
    const float2 a = g_a[p];
    float2 cc = cmul(a, g_carry[c * P_STATE + p]);
    size_t base = (size_t)c * T_CHUNK * P_STATE + p;
    #pragma unroll 8
    for (int t = 0; t < T_CHUNK; t++) {
        float2 v = g_Bu[base + (size_t)t * P_STATE];
        v.x += cc.x;
        v.y += cc.y;
        g_Bu[base + (size_t)t * P_STATE] = v;
        cc = cmul(cc, a);
    }
}

// ---------------------------------------------------------------------------
extern "C" void kernel_launch(void* const* d_in, const int* in_sizes, int n_in,
                              void* d_out, int out_size) {
    const float* u     = (const float*)d_in[0];
    const float* lr    = (const float*)d_in[1];
    const float* li    = (const float*)d_in[2];
    const float* b     = (const float*)d_in[3];
    const float* c     = (const float*)d_in[4];
    const float* d     = (const float*)d_in[5];
    const float* delta = (const float*)d_in[6];
    float* out = (float*)d_out;

    float2* bu2;           cudaGetSymbolAddress((void**)&bu2, g_Bu);
    __nv_bfloat16* ahi;    cudaGetSymbolAddress((void**)&ahi, g_Ahi);
    __nv_bfloat16* alo;    cudaGetSymbolAddress((void**)&alo, g_Alo);
    __nv_bfloat16* w1hi;   cudaGetSymbolAddress((void**)&w1hi, g_W1hi);
    __nv_bfloat16* w1lo;   cudaGetSymbolAddress((void**)&w1lo, g_W1lo);
    __nv_bfloat16* w2hi;   cudaGetSymbolAddress((void**)&w2hi, g_W2hi);
    __nv_bfloat16* w2lo;   cudaGetSymbolAddress((void**)&w2lo, g_W2lo);
    float* buf = (float*)bu2;

    cudaFuncSetAttribute(gemm_bf16<false>, cudaFuncAttributeMaxDynamicSharedMemorySize, SMEMB);
    cudaFuncSetAttribute(gemm_bf16<true>,  cudaFuncAttributeMaxDynamicSharedMemorySize, SMEMB);

    const int N4 = L_SEQ * N2 / 4;

    prep_params<<<1, P_STATE>>>(lr, li, delta);
    prep_weights<<<P_STATE, H_FEAT>>>(b, c);
    convert_split<<<2048, 256>>>((const float4*)u, (uint2*)ahi, (uint2*)alo, N4);
    gemm_bf16<false><<<dim3(N2 / BN, L_SEQ / BM), 256, SMEMB>>>(
        ahi, alo, w1hi, w1lo, buf, nullptr, nullptr);
    scan_kernel<<<C_CHUNKS, P_STATE>>>();
    carry_kernel<<<P_STATE, C_CHUNKS>>>();
    correct_kernel<<<C_CHUNKS - 1, P_STATE>>>();
    convert_split<<<2048, 256>>>((const float4*)buf, (uint2*)ahi, (uint2*)alo, N4);
    gemm_bf16<true><<<dim3(H_FEAT / BN, L_SEQ / BM), 256, SMEMB>>>(
        ahi, alo, w2hi, w2lo, out, u, d);
}

// round 4
// speedup vs baseline: 1.8814x; 1.0018x over previous
#include <cuda_runtime.h>
#include <cuda_bf16.h>
#include <cstdint>

// ---------------------------------------------------------------------------
// S5 SSM: ys = 2*Re( scan(Lam_bar, B_bar@u) @ C^T ) + d*u
// GEMMs: warp-level mma.sync bf16 (hi/lo split, 3 terms, fp32 accum)
// R4: term-major MMA ordering (acc ILP), 512-thr 128x256 blocks,
//     correct+convert fusion
// ---------------------------------------------------------------------------

#define L_SEQ   32768
#define H_FEAT  512
#define P_STATE 256
#define N2      512
#define C_CHUNKS 512
#define T_CHUNK  64
#define SQ_POW   6

#define BM 128
#define BN 256
#define BK 32               // bf16 elems per K-chunk
#define NCH 16              // 512 / 32
#define ROWB 80             // padded smem row bytes (64B data + 16B pad)
#define OFF_AH 0
#define OFF_AL (128 * ROWB)                  // 10240
#define OFF_BH (2 * 128 * ROWB)              // 20480
#define OFF_BL (2 * 128 * ROWB + 256 * ROWB) // 40960
#define STG_BYTES (2 * 128 * ROWB + 2 * 256 * ROWB)   // 61440
#define NSTAGE 3
#define SMEMB (NSTAGE * STG_BYTES)           // 184320

// Scratch (static __device__; no cudaMalloc allowed)
__device__ float2 g_Bu[L_SEQ * P_STATE];               // 64 MB (Bu then xs)
__device__ __nv_bfloat16 g_Ahi[L_SEQ * N2];            // 32 MB
__device__ __nv_bfloat16 g_Alo[L_SEQ * N2];            // 32 MB
__device__ __nv_bfloat16 g_W1hi[N2 * H_FEAT], g_W1lo[N2 * H_FEAT];
__device__ __nv_bfloat16 g_W2hi[H_FEAT * N2], g_W2lo[H_FEAT * N2];
__device__ float2 g_a[P_STATE];
__device__ float2 g_aT[P_STATE];
__device__ float2 g_Bscale[P_STATE];
__device__ float2 g_end[C_CHUNKS * P_STATE];
__device__ float2 g_carry[C_CHUNKS * P_STATE];

__device__ __forceinline__ float2 cmul(float2 a, float2 b) {
    return make_float2(a.x * b.x - a.y * b.y, a.x * b.y + a.y * b.x);
}

__device__ __forceinline__ uint32_t smem_u32(const void* p) {
    uint32_t a;
    asm("{ .reg .u64 t; cvta.to.shared.u64 t, %1; cvt.u32.u64 %0, t; }"
        : "=r"(a) : "l"(p));
    return a;
}
__device__ __forceinline__ void cp16(uint32_t dst, const void* src) {
    asm volatile("cp.async.cg.shared.global [%0], [%1], 16;" :: "r"(dst), "l"(src));
}
__device__ __forceinline__ void ldsm4(uint32_t* r, uint32_t addr) {
    asm volatile("ldmatrix.sync.aligned.m8n8.x4.shared.b16 {%0,%1,%2,%3}, [%4];"
                 : "=r"(r[0]), "=r"(r[1]), "=r"(r[2]), "=r"(r[3]) : "r"(addr));
}
__device__ __forceinline__ void mma16816(float* d, const uint32_t* a,
                                         uint32_t b0, uint32_t b1) {
    asm volatile(
        "mma.sync.aligned.m16n8k16.row.col.f32.bf16.bf16.f32 "
        "{%0,%1,%2,%3}, {%4,%5,%6,%7}, {%8,%9}, {%0,%1,%2,%3};"
        : "+f"(d[0]), "+f"(d[1]), "+f"(d[2]), "+f"(d[3])
        : "r"(a[0]), "r"(a[1]), "r"(a[2]), "r"(a[3]), "r"(b0), "r"(b1));
}

// ---------------------------------------------------------------------------
__global__ void prep_params(const float* __restrict__ lr,
                            const float* __restrict__ li,
                            const float* __restrict__ delta) {
    int p = threadIdx.x;
    float step = expf(delta[p]);
    float hs = 0.5f * step;
    float dr = 1.0f - hs * lr[p];
    float di = -hs * li[p];
    float inv = 1.0f / (dr * dr + di * di);
    float2 BL = make_float2(dr * inv, -di * inv);
    float2 num = make_float2(1.0f + hs * lr[p], hs * li[p]);
    float2 a = cmul(BL, num);
    g_a[p] = a;
    g_Bscale[p] = make_float2(BL.x * step, BL.y * step);
    float2 t = a;
    #pragma unroll
    for (int i = 0; i < SQ_POW; i++) t = cmul(t, t);
    g_aT[p] = t;
}

__device__ __forceinline__ void store_split(__nv_bfloat16* hi, __nv_bfloat16* lo,
                                            int idx, float v) {
    __nv_bfloat16 h = __float2bfloat16(v);
    hi[idx] = h;
    lo[idx] = __float2bfloat16(v - __bfloat162float(h));
}

__global__ void prep_weights(const float* __restrict__ b,
                             const float* __restrict__ c) {
    int p = blockIdx.x;        // 0..255
    int h = threadIdx.x;       // 0..511
    float2 bs = g_Bscale[p];
    float br = b[(p * H_FEAT + h) * 2 + 0];
    float bi = b[(p * H_FEAT + h) * 2 + 1];
    store_split(g_W1hi, g_W1lo, (2 * p) * H_FEAT + h, bs.x * br - bs.y * bi);
    store_split(g_W1hi, g_W1lo, (2 * p + 1) * H_FEAT + h, bs.x * bi + bs.y * br);
    store_split(g_W2hi, g_W2lo, h * N2 + 2 * p,      2.0f * c[(h * P_STATE + p) * 2 + 0]);
    store_split(g_W2hi, g_W2lo, h * N2 + 2 * p + 1, -2.0f * c[(h * P_STATE + p) * 2 + 1]);
}

// fp32 -> bf16 hi/lo split (grid-stride, float4)
__global__ void convert_split(const float4* __restrict__ src,
                              uint2* __restrict__ hi, uint2* __restrict__ lo, int n4) {
    int stride = gridDim.x * blockDim.x;
    for (int i = blockIdx.x * blockDim.x + threadIdx.x; i < n4; i += stride) {
        float4 v = src[i];
        __nv_bfloat162 h0 = __floats2bfloat162_rn(v.x, v.y);
        __nv_bfloat162 h1 = __floats2bfloat162_rn(v.z, v.w);
        float2 f0 = __bfloat1622float2(h0);
        float2 f1 = __bfloat1622float2(h1);
        __nv_bfloat162 l0 = __floats2bfloat162_rn(v.x - f0.x, v.y - f0.y);
        __nv_bfloat162 l1 = __floats2bfloat162_rn(v.z - f1.x, v.w - f1.y);
        hi[i] = make_uint2(*(uint32_t*)&h0, *(uint32_t*)&h1);
        lo[i] = make_uint2(*(uint32_t*)&l0, *(uint32_t*)&l1);
    }
}

// ---------------------------------------------------------------------------
// bf16 split GEMM: C[M,512] = (Ah+Al)[M,K] x (Bh+Bl)[N,K]^T
// block 128x256, 512 thr (4x4 warps of 32x64), K-chunks 32, 3-stage cp.async
// ---------------------------------------------------------------------------
template <bool EPI>
__global__ void __launch_bounds__(512, 1)
gemm_bf16(const __nv_bfloat16* __restrict__ Ahi, const __nv_bfloat16* __restrict__ Alo,
          const __nv_bfloat16* __restrict__ Bhi, const __nv_bfloat16* __restrict__ Blo,
          float* __restrict__ Cout, const float* __restrict__ U,
          const float* __restrict__ D) {
    extern __shared__ char smem[];
    const uint32_t sb = smem_u32(smem);
    const int tid = threadIdx.x;
    const int wid = tid >> 5, lane = tid & 31;
    const int warpM = wid & 3, warpN = wid >> 2;       // 4x4 warp grid
    const int bm = blockIdx.y * BM;
    const int bn = blockIdx.x * BN;

    const char* baseAh = (const char*)Ahi + (size_t)bm * 1024;
    const char* baseAl = (const char*)Alo + (size_t)bm * 1024;
    const char* baseBh = (const char*)Bhi + (size_t)bn * 1024;
    const char* baseBl = (const char*)Blo + (size_t)bn * 1024;

    const int s = tid & 3;          // 16B segment
    const int r = tid >> 2;         // 0..127
    auto load_chunk = [&](int kt, int st) {
        const uint32_t base = sb + st * STG_BYTES;
        const int kb = kt * 64;     // byte offset into 1024B row
        const uint32_t so = r * ROWB + s * 16;
        const size_t go = (size_t)r * 1024 + kb + s * 16;
        cp16(base + OFF_AH + so, baseAh + go);
        cp16(base + OFF_AL + so, baseAl + go);
        cp16(base + OFF_BH + so, baseBh + go);
        cp16(base + OFF_BH + so + 128 * ROWB, baseBh + go + 128 * 1024);
        cp16(base + OFF_BL + so, baseBl + go);
        cp16(base + OFF_BL + so + 128 * ROWB, baseBl + go + 128 * 1024);
        asm volatile("cp.async.commit_group;");
    };

    load_chunk(0, 0);
    load_chunk(1, 1);

    float acc[2][8][4];
    #pragma unroll
    for (int im = 0; im < 2; im++)
        #pragma unroll
        for (int in = 0; in < 8; in++)
            #pragma unroll
            for (int q = 0; q < 4; q++) acc[im][in][q] = 0.0f;

    const uint32_t a_lo = (lane & 15) * ROWB + (lane >> 4) * 16;
    const uint32_t b_lo = ((lane & 7) + ((lane >> 4) << 3)) * ROWB +
                          ((lane >> 3) & 1) * 16;

    for (int kt = 0; kt < NCH; kt++) {
        const int st = kt % NSTAGE;
        if (kt == NCH - 1) asm volatile("cp.async.wait_group 0;");
        else               asm volatile("cp.async.wait_group 1;");
        __syncthreads();
        if (kt + 2 < NCH) load_chunk(kt + 2, (kt + 2) % NSTAGE);

        const uint32_t sg = sb + st * STG_BYTES;
        #pragma unroll
        for (int ks = 0; ks < 2; ks++) {
            const uint32_t ksb = ks * 32;
            uint32_t ah[2][4], al[2][4], bh[4][4], bl[4][4];
            #pragma unroll
            for (int im = 0; im < 2; im++) {
                const uint32_t ao = (warpM * 32 + im * 16) * ROWB + a_lo + ksb;
                ldsm4(ah[im], sg + OFF_AH + ao);
                ldsm4(al[im], sg + OFF_AL + ao);
            }
            #pragma unroll
            for (int ip = 0; ip < 4; ip++) {
                const uint32_t bo = (warpN * 64 + ip * 16) * ROWB + b_lo + ksb;
                ldsm4(bh[ip], sg + OFF_BH + bo);
                ldsm4(bl[ip], sg + OFF_BL + bo);
            }
            // term-major ordering: 16 independent accumulators per term
            #pragma unroll
            for (int im = 0; im < 2; im++)
                #pragma unroll
                for (int ip = 0; ip < 4; ip++) {
                    mma16816(acc[im][2 * ip],     ah[im], bh[ip][0], bh[ip][1]);
                    mma16816(acc[im][2 * ip + 1], ah[im], bh[ip][2], bh[ip][3]);
                }
            #pragma unroll
            for (int im = 0; im < 2; im++)
                #pragma unroll
                for (int ip = 0; ip < 4; ip++) {
                    mma16816(acc[im][2 * ip],     ah[im], bl[ip][0], bl[ip][1]);
                    mma16816(acc[im][2 * ip + 1], ah[im], bl[ip][2], bl[ip][3]);
                }
            #pragma unroll
            for (int im = 0; im < 2; im++)
                #pragma unroll
                for (int ip = 0; ip < 4; ip++) {
                    mma16816(acc[im][2 * ip],     al[im], bh[ip][0], bh[ip][1]);
                    mma16816(acc[im][2 * ip + 1], al[im], bh[ip][2], bh[ip][3]);
                }
        }
    }

    #pragma unroll
    for (int im = 0; im < 2; im++) {
        const int row0 = bm + warpM * 32 + im * 16 + (lane >> 2);
        #pragma unroll
        for (int in = 0; in < 8; in++) {
            const int col = bn + warpN * 64 + in * 8 + (lane & 3) * 2;
            float2 v0 = make_float2(acc[im][in][0], acc[im][in][1]);
            float2 v1 = make_float2(acc[im][in][2], acc[im][in][3]);
            if constexpr (EPI) {
                float2 dv = *(const float2*)&D[col];
                float2 u0 = *(const float2*)&U[(size_t)row0 * H_FEAT + col];
                float2 u1 = *(const float2*)&U[(size_t)(row0 + 8) * H_FEAT + col];
                v0.x = fmaf(dv.x, u0.x, v0.x); v0.y = fmaf(dv.y, u0.y, v0.y);
                v1.x = fmaf(dv.x, u1.x, v1.x); v1.y = fmaf(dv.y, u1.y, v1.y);
            }
            *(float2*)&Cout[(size_t)row0 * H_FEAT + col] = v0;
            *(float2*)&Cout[(size_t)(row0 + 8) * H_FEAT + col] = v1;
        }
    }
}

// ---------------------------------------------------------------------------
// Chunked recurrence scan
// ---------------------------------------------------------------------------
__global__ void __launch_bounds__(256) scan_kernel() {
    const int p = threadIdx.x;
    const int c = blockIdx.x;
    const float2 a = g_a[p];
    float2 x = make_float2(0.0f, 0.0f);
    size_t base = (size_t)c * T_CHUNK * P_STATE + p;
    #pragma unroll 8
    for (int t = 0; t < T_CHUNK; t++) {
        float2 v = g_Bu[base + (size_t)t * P_STATE];
        float xr = fmaf(a.x, x.x, fmaf(-a.y, x.y, v.x));
        float xi = fmaf(a.x, x.y, fmaf(a.y, x.x, v.y));
        x = make_float2(xr, xi);
        g_Bu[base + (size_t)t * P_STATE] = x;
    }
    g_end[c * P_STATE + p] = x;
}

__global__ void __launch_bounds__(C_CHUNKS) carry_kernel() {
    __shared__ float2 s[C_CHUNKS];
    const int p = blockIdx.x;
    const int c = threadIdx.x;
    const float2 aT = g_aT[p];
    s[c] = g_end[c * P_STATE + p];
    float2 m = aT;
    __syncthreads();
    for (int d = 1; d < C_CHUNKS; d <<= 1) {
        float2 other = make_float2(0.0f, 0.0f);
        if (c >= d) other = s[c - d];
        __syncthreads();
        if (c >= d) {
            float2 cur = s[c];
            s[c] = make_float2(cur.x + m.x * other.x - m.y * other.y,
                               cur.y + m.x * other.y + m.y * other.x);
        }
        m = cmul(m, m);
        __syncthreads();
    }
    float2 ci = make_float2(0.0f, 0.0f);
    if (c > 0) ci = s[c - 1];
    g_carry[c * P_STATE + p] = ci;
}

// Fused: x_global = x_local + a^{t+1}*carry, then bf16 hi/lo split to Ahi/Alo
__global__ void __launch_bounds__(256) correct_convert_kernel() {
    const int p = threadIdx.x;
    const int c = blockIdx.x;
    const float2 a = g_a[p];
    float2 cc = cmul(a, g_carry[c * P_STATE + p]);   // zero for c==0
    const size_t base = (size_t)c * T_CHUNK * P_STATE + p;
    uint32_t* hi = (uint32_t*)g_Ahi;
    uint32_t* lo = (uint32_t*)g_Alo;
    #pragma unroll 4
    for (int t = 0; t < T_CHUNK; t++) {
        float2 v = g_Bu[base + (size_t)t * P_STATE];
        v.x += cc.x;
        v.y += cc.y;
        const size_t idx = base + (size_t)t * P_STATE;   // == l*256 + p
        __nv_bfloat162 h = __floats2bfloat162_rn(v.x, v.y);
        float2 hf = __bfloat1622float2(h);
        __nv_bfloat162 l2 = __floats2bfloat162_rn(v.x - hf.x, v.y - hf.y);
        hi[idx] = *(uint32_t*)&h;
        lo[idx] = *(uint32_t*)&l2;
        cc = cmul(cc, a);
    }
}

// ---------------------------------------------------------------------------
extern "C" void kernel_launch(void* const* d_in, const int* in_sizes, int n_in,
                              void* d_out, int out_size) {
    const float* u     = (const float*)d_in[0];
    const float* lr    = (const float*)d_in[1];
    const float* li    = (const float*)d_in[2];
    const float* b     = (const float*)d_in[3];
    const float* c     = (const float*)d_in[4];
    const float* d     = (const float*)d_in[5];
    const float* delta = (const float*)d_in[6];
    float* out = (float*)d_out;

    float2* bu2;           cudaGetSymbolAddress((void**)&bu2, g_Bu);
    __nv_bfloat16* ahi;    cudaGetSymbolAddress((void**)&ahi, g_Ahi);
    __nv_bfloat16* alo;    cudaGetSymbolAddress((void**)&alo, g_Alo);
    __nv_bfloat16* w1hi;   cudaGetSymbolAddress((void**)&w1hi, g_W1hi);
    __nv_bfloat16* w1lo;   cudaGetSymbolAddress((void**)&w1lo, g_W1lo);
    __nv_bfloat16* w2hi;   cudaGetSymbolAddress((void**)&w2hi, g_W2hi);
    __nv_bfloat16* w2lo;   cudaGetSymbolAddress((void**)&w2lo, g_W2lo);
    float* buf = (float*)bu2;

    cudaFuncSetAttribute(gemm_bf16<false>, cudaFuncAttributeMaxDynamicSharedMemorySize, SMEMB);
    cudaFuncSetAttribute(gemm_bf16<true>,  cudaFuncAttributeMaxDynamicSharedMemorySize, SMEMB);

    const int N4 = L_SEQ * N2 / 4;

    prep_params<<<1, P_STATE>>>(lr, li, delta);
    prep_weights<<<P_STATE, H_FEAT>>>(b, c);
    convert_split<<<2048, 256>>>((const float4*)u, (uint2*)ahi, (uint2*)alo, N4);
    gemm_bf16<false><<<dim3(N2 / BN, L_SEQ / BM), 512, SMEMB>>>(
        ahi, alo, w1hi, w1lo, buf, nullptr, nullptr);
    scan_kernel<<<C_CHUNKS, P_STATE>>>();
    carry_kernel<<<P_STATE, C_CHUNKS>>>();
    correct_convert_kernel<<<C_CHUNKS, P_STATE>>>();
    gemm_bf16<true><<<dim3(H_FEAT / BN, L_SEQ / BM), 512, SMEMB>>>(
        ahi, alo, w2hi, w2lo, out, u, d);
}